// round 6
// baseline (speedup 1.0000x reference)
#include <cuda_runtime.h>
#include <math.h>

#define N_NODESC 20000
#define N_EDGESC 120000
#define HY_STRIDE 44

// ---- static device scratch ----
__device__ int   g_deg[N_NODESC];
__device__ int   g_off[N_NODESC + 1];
__device__ int   g_cursor[N_NODESC];
__device__ int2  g_edge[N_EDGESC];
__device__ float g_MW[16 * 384];
__device__ float g_R[(size_t)N_NODESC * 384];
__device__ float g_hy[(size_t)N_EDGESC * HY_STRIDE + 16];
__device__ float g_T[(size_t)N_NODESC * 384];
__device__ unsigned g_bcount = 0;
__device__ unsigned g_bsense = 0;

#define C_EMB   8.4335730690754870f
#define C_V     0.05103103630798287f
#define C_LOGIT 0.003189439769248930f

__device__ __forceinline__ float susf(float v) {
    return (v > 0.f) ? __expf(-__fdividef(1.f, v)) : 0.f;
}
__device__ __forceinline__ float siluf(float z) {
    return __fdividef(z, 1.f + __expf(-z));
}

// sense-reversing grid barrier (must be called an EVEN number of times per launch)
__device__ __forceinline__ void grid_bar(unsigned& ls, unsigned nblk) {
    __syncthreads();
    if (threadIdx.x == 0) {
        ls ^= 1u;
        __threadfence();
        unsigned old = atomicAdd(&g_bcount, 1u);
        if (old == nblk - 1u) {
            g_bcount = 0u;
            __threadfence();
            atomicExch(&g_bsense, ls);
        } else {
            volatile unsigned* vs = &g_bsense;
            while (*vs != ls) __nanosleep(64);
        }
        __threadfence();
    }
    __syncthreads();
}

__global__ void __launch_bounds__(1024, 1)
k_all(const float* __restrict__ x, const float* __restrict__ pos,
      const float* __restrict__ Wq, const float* __restrict__ Wk1,
      const float* __restrict__ Wk2, const float* __restrict__ Wv1,
      const float* __restrict__ Wv2, const float* __restrict__ Wdot,
      const int* __restrict__ esrc, const int* __restrict__ edst,
      float* __restrict__ out) {
    __shared__ float s_wkv[320];       // Wk1 | Wv1
    __shared__ float s_uni[6336];      // union: scan ints / sMW[16][385] / out tiles
    __shared__ float s_x0[128];
    unsigned ls = 0;
    const unsigned nb = gridDim.x;
    const int tid = threadIdx.x;
    const int gtid = blockIdx.x * 1024 + tid;
    const int gsz = nb * 1024;

    // ---------- P0: zero deg, compute MW, stage Wk1/Wv1 ----------
    for (int i = gtid; i < N_NODESC; i += gsz) g_deg[i] = 0;
    if (gtid < 384) {
        int t = gtid, j = t / 24, u = t - j * 24;
        float wk[16];
        #pragma unroll
        for (int w = 0; w < 16; w++) wk[w] = __ldg(&Wk2[j * 384 + u * 16 + w]);
        #pragma unroll
        for (int p = 0; p < 16; p++) {
            float a = 0.f;
            #pragma unroll
            for (int w = 0; w < 16; w++) {
                float m = 0.f;
                #pragma unroll
                for (int r = 0; r < 16; r++)
                    m += __ldg(&Wq[p * 16 + r]) * __ldg(&Wdot[r * 16 + w]);
                a += m * (0.25f * C_LOGIT) * wk[w];
            }
            g_MW[p * 384 + t] = a;
        }
    }
    if (tid < 160) { s_wkv[tid] = __ldg(&Wk1[tid]); s_wkv[160 + tid] = __ldg(&Wv1[tid]); }
    grid_bar(ls, nb);

    // ---------- P1: histogram ----------
    for (int i = gtid; i < N_EDGESC; i += gsz) atomicAdd(&g_deg[edst[i]], 1);
    grid_bar(ls, nb);

    // ---------- P2: scan (block 0 only) ----------
    if (blockIdx.x == 0) {
        int* s = (int*)s_uni;
        const int CH = (N_NODESC + 1023) / 1024;  // 20
        int base = tid * CH;
        int sum = 0;
        #pragma unroll
        for (int c = 0; c < CH; c++) {
            int idx = base + c;
            if (idx < N_NODESC) sum += g_deg[idx];
        }
        s[tid] = sum;
        __syncthreads();
        for (int d = 1; d < 1024; d <<= 1) {
            int v = (tid >= d) ? s[tid - d] : 0;
            __syncthreads();
            s[tid] += v;
            __syncthreads();
        }
        int run = s[tid] - sum;
        for (int c = 0; c < CH; c++) {
            int idx = base + c;
            if (idx < N_NODESC) {
                g_off[idx] = run;
                g_cursor[idx] = run;
                run += g_deg[idx];
            }
        }
        if (tid == 1023) g_off[N_NODESC] = s[1023];
    }
    grid_bar(ls, nb);

    // ---------- P3: scatter ----------
    for (int i = gtid; i < N_EDGESC; i += gsz) {
        int d = edst[i];
        int p = atomicAdd(&g_cursor[d], 1);
        g_edge[p] = make_int2(esrc[i], d);
    }
    grid_bar(ls, nb);

    // ---------- P4: R GEMM ----------
    {
        float* sMW = s_uni;  // [16][385]
        for (int i = tid; i < 16 * 384; i += 1024) {
            int p = i / 384, t = i - p * 384;
            sMW[p * 385 + t] = g_MW[i];
        }
        __syncthreads();
        int nchunk = (N_NODESC + 7) / 8;
        for (int c = blockIdx.x; c < nchunk; c += nb) {
            int n0 = c * 8;
            if (tid < 128) {
                int nn = tid >> 4, cc = tid & 15;
                s_x0[tid] = (n0 + nn < N_NODESC) ? x[(size_t)(n0 + nn) * 40 + cc] : 0.f;
            }
            __syncthreads();
            int ni = tid >> 7;       // 0..7
            int o = tid & 127;
            int n = n0 + ni;
            if (n < N_NODESC) {
                const float* xq = s_x0 + ni * 16;
                #pragma unroll
                for (int rep = 0; rep < 3; rep++) {
                    int oo = o + rep * 128;
                    float a = 0.f;
                    #pragma unroll
                    for (int p = 0; p < 16; p++) a += xq[p] * sMW[p * 385 + oo];
                    g_R[(size_t)n * 384 + oo] = a;
                }
            }
            __syncthreads();
        }
    }
    grid_bar(ls, nb);

    // ---------- P5: passA (edge-parallel) ----------
    for (int i = gtid; i < N_EDGESC; i += gsz) {
        int2 sd = g_edge[i];
        int s = sd.x, d = sd.y;
        float* row = g_hy + (size_t)i * HY_STRIDE;

        float ev0 = pos[s * 3 + 0] - pos[d * 3 + 0];
        float ev1 = pos[s * 3 + 1] - pos[d * 3 + 1];
        float ev2 = pos[s * 3 + 2] - pos[d * 3 + 2];
        float elen = sqrtf(ev0 * ev0 + ev1 * ev1 + ev2 * ev2 + 1e-12f);

        float wcut = susf(10.f * (1.f - elen * 0.25f));
        if (!(wcut > 0.f)) {
            float4 z4 = make_float4(0.f, 0.f, 0.f, 0.f);
            ((float4*)row)[0] = z4; ((float4*)row)[1] = z4;
            ((float4*)row)[2] = z4; ((float4*)row)[3] = z4;
            ((float4*)row)[10] = z4;
            continue;
        }

        float tt = elen * 2.75f;
        int b0 = (int)tt;
        float d0 = tt - (float)b0;
        float g0 = (b0 >= 1 && b0 <= 10) ? (C_EMB * susf(d0 + 1.f) * susf(1.f - d0)) : 0.f;
        float g1 = (b0 >= 0 && b0 <= 9)  ? (C_EMB * susf(d0) * susf(2.f - d0)) : 0.f;
        int r0 = b0 - 1; if (r0 < 0) r0 = 0; if (r0 > 9) r0 = 9;
        int r1 = b0;     if (r1 < 0) r1 = 0; if (r1 > 9) r1 = 9;

        float4 xr[10];
        const float4* xp4 = (const float4*)(x + (size_t)s * 40);
        #pragma unroll
        for (int q = 0; q < 10; q++) xr[q] = __ldg(&xp4[q]);
        const float* xf = (const float*)xr;

        float y[24];
        float rinv = __frcp_rn(elen);
        #pragma unroll
        for (int u = 0; u < 16; u++) y[u] = xf[u];
        #pragma unroll
        for (int u = 0; u < 8; u++)
            y[16 + u] = (xf[16 + u * 3] * ev0 + xf[17 + u * 3] * ev1 + xf[18 + u * 3] * ev2) * rinv;

        float lg = 0.f;
        const float4* Rp = (const float4*)(g_R + (size_t)d * 384);
        #pragma unroll
        for (int j = 0; j < 16; j++) {
            float zk = g0 * s_wkv[r0 * 16 + j] + g1 * s_wkv[r1 * 16 + j];
            float hk = siluf(zk);
            float Sj = 0.f;
            #pragma unroll
            for (int q4 = 0; q4 < 6; q4++) {
                float4 r4 = __ldg(&Rp[j * 6 + q4]);
                Sj += r4.x * y[q4 * 4 + 0] + r4.y * y[q4 * 4 + 1]
                    + r4.z * y[q4 * 4 + 2] + r4.w * y[q4 * 4 + 3];
            }
            lg += hk * Sj;
        }
        float expv = wcut * __expf(lg);
        float sev = sqrtf(expv);

        #pragma unroll
        for (int j4 = 0; j4 < 4; j4++) {
            float h0 = sev * siluf(g0 * s_wkv[160 + r0 * 16 + j4 * 4 + 0] + g1 * s_wkv[160 + r1 * 16 + j4 * 4 + 0]);
            float h1 = sev * siluf(g0 * s_wkv[160 + r0 * 16 + j4 * 4 + 1] + g1 * s_wkv[160 + r1 * 16 + j4 * 4 + 1]);
            float h2 = sev * siluf(g0 * s_wkv[160 + r0 * 16 + j4 * 4 + 2] + g1 * s_wkv[160 + r1 * 16 + j4 * 4 + 2]);
            float h3 = sev * siluf(g0 * s_wkv[160 + r0 * 16 + j4 * 4 + 3] + g1 * s_wkv[160 + r1 * 16 + j4 * 4 + 3]);
            ((float4*)row)[j4] = make_float4(h0, h1, h2, h3);
        }
        #pragma unroll
        for (int q4 = 0; q4 < 6; q4++)
            ((float4*)(row + 16))[q4] = make_float4(y[q4 * 4 + 0], y[q4 * 4 + 1],
                                                    y[q4 * 4 + 2], y[q4 * 4 + 3]);
        ((float4*)row)[10] = make_float4(expv, 0.f, 0.f, 0.f);
    }
    grid_bar(ls, nb);

    // ---------- P6: passB (warp per node) ----------
    {
        int l = tid & 31;
        int wid = blockIdx.x * 32 + (tid >> 5);
        int nwarp = nb * 32;
        int par = l >> 4;
        int jj = l & 15;
        for (int n = wid; n < N_NODESC; n += nwarp) {
            int beg = g_off[n], end = g_off[n + 1];
            float acc[12];
            #pragma unroll
            for (int k = 0; k < 12; k++) acc[k] = 0.f;
            float z = 0.f;
            for (int i = beg; i < end; i++) {
                const float* row = g_hy + (size_t)i * HY_STRIDE;
                float A = row[l];
                float B = (l < 16) ? row[32 + l] : 0.f;
                z += __shfl_sync(0xffffffffu, B, 8);
                float hval = __shfl_sync(0xffffffffu, A, jj);
                #pragma unroll
                for (int k = 0; k < 8; k++) {
                    float yv = __shfl_sync(0xffffffffu, A, 16 + par + 2 * k);
                    acc[k] += hval * yv;
                }
                #pragma unroll
                for (int k = 8; k < 12; k++) {
                    float yv = __shfl_sync(0xffffffffu, B, par + 2 * k - 16);
                    acc[k] += hval * yv;
                }
            }
            if (z == 0.f) z = 1.f;
            float sc = rsqrtf(z);
            float* Tp = g_T + (size_t)n * 384;
            #pragma unroll
            for (int k = 0; k < 12; k++) Tp[l + 32 * k] = acc[k] * sc;
        }
    }
    grid_bar(ls, nb);

    // ---------- P7: output GEMM ----------
    {
        float* sW = s_uni;             // [32][36]
        float* sT = s_uni + 32 * 36;   // [128][36]
        int c0 = tid & 31;
        int g = tid >> 5;              // 0..31, nodes g*4..g*4+3
        int ntile = (N_NODESC + 127) / 128;
        for (int tile = blockIdx.x; tile < ntile; tile += nb) {
            int base = tile * 128;
            float acc[4] = {0.f, 0.f, 0.f, 0.f};
            for (int kc = 0; kc < 12; kc++) {
                __syncthreads();
                {
                    int kkl = tid >> 5, col = tid & 31;
                    int k = kc * 32 + kkl;
                    sW[col * 36 + kkl] = __ldg(&Wv2[(k & 15) * 768 + (k >> 4) * 32 + col]);
                }
                #pragma unroll
                for (int q = 0; q < 4; q++) {
                    int i = q * 1024 + tid;
                    int node = i >> 5, kkl = i & 31;
                    int n = base + node;
                    sT[node * 36 + kkl] = (n < N_NODESC) ? g_T[(size_t)n * 384 + kc * 32 + kkl] : 0.f;
                }
                __syncthreads();
                #pragma unroll
                for (int kk4 = 0; kk4 < 8; kk4++) {
                    float4 w0 = ((const float4*)(sW + c0 * 36))[kk4];
                    #pragma unroll
                    for (int i2 = 0; i2 < 4; i2++) {
                        float4 tv = ((const float4*)(sT + (g * 4 + i2) * 36))[kk4];
                        acc[i2] += tv.x * w0.x + tv.y * w0.y + tv.z * w0.z + tv.w * w0.w;
                    }
                }
            }
            #pragma unroll
            for (int i2 = 0; i2 < 4; i2++) {
                int n = base + g * 4 + i2;
                if (n < N_NODESC) out[n * 32 + c0] = acc[i2] * C_V;
            }
            __syncthreads();
        }
    }
    grid_bar(ls, nb);   // pad barrier -> even count (8), restores sense to 0
}

// ---------------- launch ----------------
extern "C" void kernel_launch(void* const* d_in, const int* in_sizes, int n_in,
                              void* d_out, int out_size) {
    (void)in_sizes; (void)n_in; (void)out_size;
    const float* x    = (const float*)d_in[0];
    const float* pos  = (const float*)d_in[1];
    const float* Wq   = (const float*)d_in[2];
    const float* Wk1  = (const float*)d_in[3];
    const float* Wk2  = (const float*)d_in[4];
    const float* Wv1  = (const float*)d_in[5];
    const float* Wv2  = (const float*)d_in[6];
    const float* Wdot = (const float*)d_in[7];
    const int* esrc   = (const int*)d_in[8];
    const int* edst   = (const int*)d_in[9];
    float* out = (float*)d_out;

    int dev = 0, sm = 148;
    cudaGetDevice(&dev);
    cudaDeviceGetAttribute(&sm, cudaDevAttrMultiProcessorCount, dev);

    k_all<<<sm, 1024>>>(x, pos, Wq, Wk1, Wk2, Wv1, Wv2, Wdot, esrc, edst, out);
}

// round 7
// speedup vs baseline: 1.2215x; 1.2215x over previous
#include <cuda_runtime.h>
#include <math.h>

#define N_NODESC 20000
#define N_EDGESC 120000
#define HY_STRIDE 44

// ---- static device scratch ----
__device__ int   g_deg[N_NODESC];
__device__ int   g_off[N_NODESC + 1];
__device__ int   g_cursor[N_NODESC];
__device__ int2  g_edge[N_EDGESC];
__device__ float g_MW[16 * 384];
__device__ float g_R[(size_t)N_NODESC * 384];
__device__ float g_hy[(size_t)N_EDGESC * HY_STRIDE + 16];
__device__ float g_T[(size_t)N_NODESC * 384];
__device__ unsigned g_bcount = 0;
__device__ unsigned g_bsense = 0;

#define C_EMB   8.4335730690754870f
#define C_V     0.05103103630798287f
#define C_LOGIT 0.003189439769248930f

__device__ __forceinline__ float susf(float v) {
    return (v > 0.f) ? __expf(-__fdividef(1.f, v)) : 0.f;
}
__device__ __forceinline__ float siluf(float z) {
    return __fdividef(z, 1.f + __expf(-z));
}

// sense-reversing grid barrier (EVEN number of calls per launch)
__device__ __forceinline__ void grid_bar(unsigned& ls, unsigned nblk) {
    __syncthreads();
    if (threadIdx.x == 0) {
        ls ^= 1u;
        __threadfence();
        unsigned old = atomicAdd(&g_bcount, 1u);
        if (old == nblk - 1u) {
            g_bcount = 0u;
            __threadfence();
            atomicExch(&g_bsense, ls);
        } else {
            volatile unsigned* vs = &g_bsense;
            while (*vs != ls) __nanosleep(64);
        }
        __threadfence();
    }
    __syncthreads();
}

// ---------------- cooperative CSR build: zero+MW | hist | scan | scatter ----------------
__global__ void __launch_bounds__(1024, 1)
k_csr(const float* __restrict__ Wq, const float* __restrict__ Wdot,
      const float* __restrict__ Wk2,
      const int* __restrict__ esrc, const int* __restrict__ edst) {
    __shared__ int s_scan[1024];
    unsigned ls = 0;
    const unsigned nb = gridDim.x;
    const int tid = threadIdx.x;
    const int gtid = blockIdx.x * 1024 + tid;
    const int gsz = nb * 1024;

    // P0: zero deg everywhere; block 1 also computes MW
    for (int i = gtid; i < N_NODESC; i += gsz) g_deg[i] = 0;
    if (blockIdx.x == 1 && tid < 384) {
        int t = tid, j = t / 24, u = t - j * 24;
        float wk[16];
        #pragma unroll
        for (int w = 0; w < 16; w++) wk[w] = __ldg(&Wk2[j * 384 + u * 16 + w]);
        #pragma unroll
        for (int p = 0; p < 16; p++) {
            float a = 0.f;
            #pragma unroll
            for (int w = 0; w < 16; w++) {
                float m = 0.f;
                #pragma unroll
                for (int r = 0; r < 16; r++)
                    m += __ldg(&Wq[p * 16 + r]) * __ldg(&Wdot[r * 16 + w]);
                a += m * (0.25f * C_LOGIT) * wk[w];
            }
            g_MW[p * 384 + t] = a;
        }
    }
    grid_bar(ls, nb);

    // P1: histogram
    for (int i = gtid; i < N_EDGESC; i += gsz) atomicAdd(&g_deg[edst[i]], 1);
    grid_bar(ls, nb);

    // P2: scan (block 0 only)
    if (blockIdx.x == 0) {
        const int CH = (N_NODESC + 1023) / 1024;  // 20
        int base = tid * CH;
        int sum = 0;
        #pragma unroll
        for (int c = 0; c < CH; c++) {
            int idx = base + c;
            if (idx < N_NODESC) sum += g_deg[idx];
        }
        s_scan[tid] = sum;
        __syncthreads();
        for (int d = 1; d < 1024; d <<= 1) {
            int v = (tid >= d) ? s_scan[tid - d] : 0;
            __syncthreads();
            s_scan[tid] += v;
            __syncthreads();
        }
        int run = s_scan[tid] - sum;
        for (int c = 0; c < CH; c++) {
            int idx = base + c;
            if (idx < N_NODESC) {
                g_off[idx] = run;
                g_cursor[idx] = run;
                run += g_deg[idx];
            }
        }
        if (tid == 1023) g_off[N_NODESC] = s_scan[1023];
    }
    grid_bar(ls, nb);

    // P3: scatter
    for (int i = gtid; i < N_EDGESC; i += gsz) {
        int d = edst[i];
        int p = atomicAdd(&g_cursor[d], 1);
        g_edge[p] = make_int2(esrc[i], d);
    }
    grid_bar(ls, nb);   // pad -> 4 barriers total, sense restored to 0
}

// ---------------- R GEMM: R[n][t] = sum_p x0[n][p] * MW[p][t] ----------------
#define RT_NODES 50
__global__ void k_R(const float* __restrict__ x) {
    __shared__ float sW[16][385];
    __shared__ float sq[RT_NODES * 16];
    int t = threadIdx.x;  // 0..383

    #pragma unroll
    for (int p = 0; p < 16; p++) sW[p][t] = g_MW[p * 384 + t];

    int nb = blockIdx.x * RT_NODES;
    for (int i = t; i < RT_NODES * 16; i += 384) {
        int n = i >> 4, c = i & 15;
        sq[i] = x[(size_t)(nb + n) * 40 + c];
    }
    __syncthreads();

    float wr[16];
    #pragma unroll
    for (int p = 0; p < 16; p++) wr[p] = sW[p][t];

    float* Rp = g_R + (size_t)nb * 384 + t;
    #pragma unroll 2
    for (int n0 = 0; n0 < RT_NODES; n0++) {
        const float4* q4 = (const float4*)(sq + n0 * 16);
        float4 qa = q4[0], qb = q4[1], qc = q4[2], qdv = q4[3];
        float a = wr[0] * qa.x + wr[1] * qa.y + wr[2] * qa.z + wr[3] * qa.w
                + wr[4] * qb.x + wr[5] * qb.y + wr[6] * qb.z + wr[7] * qb.w
                + wr[8] * qc.x + wr[9] * qc.y + wr[10] * qc.z + wr[11] * qc.w
                + wr[12] * qdv.x + wr[13] * qdv.y + wr[14] * qdv.z + wr[15] * qdv.w;
        Rp[(size_t)n0 * 384] = a;
    }
}

// ---------------- pass A (edge-parallel) ----------------
__global__ void k_passA(const float* __restrict__ x, const float* __restrict__ pos,
                        const float* __restrict__ Wk1, const float* __restrict__ Wv1) {
    int i = blockIdx.x * blockDim.x + threadIdx.x;
    if (i >= N_EDGESC) return;
    int2 sd = g_edge[i];
    int s = sd.x, d = sd.y;
    float* row = g_hy + (size_t)i * HY_STRIDE;

    float ev0 = pos[s * 3 + 0] - pos[d * 3 + 0];
    float ev1 = pos[s * 3 + 1] - pos[d * 3 + 1];
    float ev2 = pos[s * 3 + 2] - pos[d * 3 + 2];
    float elen = sqrtf(ev0 * ev0 + ev1 * ev1 + ev2 * ev2 + 1e-12f);

    float wcut = susf(10.f * (1.f - elen * 0.25f));
    if (!(wcut > 0.f)) {
        float4 z4 = make_float4(0.f, 0.f, 0.f, 0.f);
        ((float4*)row)[0] = z4; ((float4*)row)[1] = z4;
        ((float4*)row)[2] = z4; ((float4*)row)[3] = z4;
        ((float4*)row)[10] = z4;
        return;
    }

    float tt = elen * 2.75f;
    int b0 = (int)tt;
    float d0 = tt - (float)b0;
    float g0 = (b0 >= 1 && b0 <= 10) ? (C_EMB * susf(d0 + 1.f) * susf(1.f - d0)) : 0.f;
    float g1 = (b0 >= 0 && b0 <= 9)  ? (C_EMB * susf(d0) * susf(2.f - d0)) : 0.f;
    int r0 = b0 - 1; if (r0 < 0) r0 = 0; if (r0 > 9) r0 = 9;
    int r1 = b0;     if (r1 < 0) r1 = 0; if (r1 > 9) r1 = 9;

    float4 xr[10];
    const float4* xp4 = (const float4*)(x + (size_t)s * 40);
    #pragma unroll
    for (int q = 0; q < 10; q++) xr[q] = __ldg(&xp4[q]);
    const float* xf = (const float*)xr;

    float y[24];
    float rinv = __frcp_rn(elen);
    #pragma unroll
    for (int u = 0; u < 16; u++) y[u] = xf[u];
    #pragma unroll
    for (int u = 0; u < 8; u++)
        y[16 + u] = (xf[16 + u * 3] * ev0 + xf[17 + u * 3] * ev1 + xf[18 + u * 3] * ev2) * rinv;

    float lg = 0.f;
    const float4* Rp = (const float4*)(g_R + (size_t)d * 384);
    #pragma unroll
    for (int j = 0; j < 16; j++) {
        float zk = g0 * __ldg(&Wk1[r0 * 16 + j]) + g1 * __ldg(&Wk1[r1 * 16 + j]);
        float hk = siluf(zk);
        float Sj = 0.f;
        #pragma unroll
        for (int q4 = 0; q4 < 6; q4++) {
            float4 r4 = __ldg(&Rp[j * 6 + q4]);
            Sj += r4.x * y[q4 * 4 + 0] + r4.y * y[q4 * 4 + 1]
                + r4.z * y[q4 * 4 + 2] + r4.w * y[q4 * 4 + 3];
        }
        lg += hk * Sj;
    }
    float expv = wcut * __expf(lg);
    float sev = sqrtf(expv);

    #pragma unroll
    for (int j4 = 0; j4 < 4; j4++) {
        float h0 = sev * siluf(g0 * __ldg(&Wv1[r0 * 16 + j4 * 4 + 0]) + g1 * __ldg(&Wv1[r1 * 16 + j4 * 4 + 0]));
        float h1 = sev * siluf(g0 * __ldg(&Wv1[r0 * 16 + j4 * 4 + 1]) + g1 * __ldg(&Wv1[r1 * 16 + j4 * 4 + 1]));
        float h2 = sev * siluf(g0 * __ldg(&Wv1[r0 * 16 + j4 * 4 + 2]) + g1 * __ldg(&Wv1[r1 * 16 + j4 * 4 + 2]));
        float h3 = sev * siluf(g0 * __ldg(&Wv1[r0 * 16 + j4 * 4 + 3]) + g1 * __ldg(&Wv1[r1 * 16 + j4 * 4 + 3]));
        ((float4*)row)[j4] = make_float4(h0, h1, h2, h3);
    }
    #pragma unroll
    for (int q4 = 0; q4 < 6; q4++)
        ((float4*)(row + 16))[q4] = make_float4(y[q4 * 4 + 0], y[q4 * 4 + 1],
                                                y[q4 * 4 + 2], y[q4 * 4 + 3]);
    ((float4*)row)[10] = make_float4(expv, 0.f, 0.f, 0.f);
}

// ---------------- pass B: single pass, warp per node ----------------
__global__ void k_passB() {
    int wwarp = threadIdx.x >> 5;
    int l = threadIdx.x & 31;
    int n = blockIdx.x * 8 + wwarp;
    if (n >= N_NODESC) return;
    int beg = g_off[n], end = g_off[n + 1];

    float acc[12];
    #pragma unroll
    for (int k = 0; k < 12; k++) acc[k] = 0.f;
    float z = 0.f;
    int par = l >> 4;
    int jj = l & 15;

    for (int i = beg; i < end; i++) {
        const float* row = g_hy + (size_t)i * HY_STRIDE;
        float A = row[l];
        float B = (l < 16) ? row[32 + l] : 0.f;
        z += __shfl_sync(0xffffffffu, B, 8);
        float hval = __shfl_sync(0xffffffffu, A, jj);
        #pragma unroll
        for (int k = 0; k < 8; k++) {
            float yv = __shfl_sync(0xffffffffu, A, 16 + par + 2 * k);
            acc[k] += hval * yv;
        }
        #pragma unroll
        for (int k = 8; k < 12; k++) {
            float yv = __shfl_sync(0xffffffffu, B, par + 2 * k - 16);
            acc[k] += hval * yv;
        }
    }

    if (z == 0.f) z = 1.f;
    float sc = rsqrtf(z);
    float* Tp = g_T + (size_t)n * 384;
    #pragma unroll
    for (int k = 0; k < 12; k++) Tp[l + 32 * k] = acc[k] * sc;
}

// ---------------- output GEMM: out = C_V * T @ W' ----------------
__global__ void k_out(const float* __restrict__ Wv2, float* __restrict__ out) {
    __shared__ __align__(16) float sW[32][36];
    __shared__ __align__(16) float sT[128][36];
    int t = threadIdx.x;                // 256
    int base = blockIdx.x * 128;
    int c0 = t & 15;
    int g = t >> 4;

    float acc[8][2];
    #pragma unroll
    for (int i2 = 0; i2 < 8; i2++) { acc[i2][0] = 0.f; acc[i2][1] = 0.f; }

    for (int kc = 0; kc < 12; kc++) {
        __syncthreads();
        #pragma unroll
        for (int q = 0; q < 4; q++) {
            int i = q * 256 + t;
            int kkl = i >> 5, col = i & 31;
            int k = kc * 32 + kkl;
            sW[col][kkl] = __ldg(&Wv2[(k & 15) * 768 + (k >> 4) * 32 + col]);
        }
        #pragma unroll
        for (int q = 0; q < 16; q++) {
            int i = q * 256 + t;
            int node = i >> 5, kkl = i & 31;
            int n = base + node;
            sT[node][kkl] = (n < N_NODESC) ? g_T[(size_t)n * 384 + kc * 32 + kkl] : 0.f;
        }
        __syncthreads();
        #pragma unroll
        for (int kk4 = 0; kk4 < 8; kk4++) {
            float4 w0 = ((const float4*)sW[c0])[kk4];
            float4 w1 = ((const float4*)sW[c0 + 16])[kk4];
            #pragma unroll
            for (int i2 = 0; i2 < 8; i2++) {
                float4 tv = ((const float4*)sT[g * 8 + i2])[kk4];
                acc[i2][0] += tv.x * w0.x + tv.y * w0.y + tv.z * w0.z + tv.w * w0.w;
                acc[i2][1] += tv.x * w1.x + tv.y * w1.y + tv.z * w1.z + tv.w * w1.w;
            }
        }
    }
    #pragma unroll
    for (int i2 = 0; i2 < 8; i2++) {
        int n = base + g * 8 + i2;
        if (n < N_NODESC) {
            out[n * 32 + c0]      = acc[i2][0] * C_V;
            out[n * 32 + c0 + 16] = acc[i2][1] * C_V;
        }
    }
}

// ---------------- launch ----------------
extern "C" void kernel_launch(void* const* d_in, const int* in_sizes, int n_in,
                              void* d_out, int out_size) {
    (void)in_sizes; (void)n_in; (void)out_size;
    const float* x    = (const float*)d_in[0];
    const float* pos  = (const float*)d_in[1];
    const float* Wq   = (const float*)d_in[2];
    const float* Wk1  = (const float*)d_in[3];
    const float* Wk2  = (const float*)d_in[4];
    const float* Wv1  = (const float*)d_in[5];
    const float* Wv2  = (const float*)d_in[6];
    const float* Wdot = (const float*)d_in[7];
    const int* esrc   = (const int*)d_in[8];
    const int* edst   = (const int*)d_in[9];
    float* out = (float*)d_out;

    int dev = 0, sm = 148;
    cudaGetDevice(&dev);
    cudaDeviceGetAttribute(&sm, cudaDevAttrMultiProcessorCount, dev);

    k_csr<<<sm, 1024>>>(Wq, Wdot, Wk2, esrc, edst);
    k_R<<<N_NODESC / RT_NODES, 384>>>(x);
    k_passA<<<(N_EDGESC + 255) / 256, 256>>>(x, pos, Wk1, Wv1);
    k_passB<<<(N_NODESC + 7) / 8, 256>>>();
    k_out<<<(N_NODESC + 127) / 128, 256>>>(Wv2, out);
}

// round 8
// speedup vs baseline: 1.3584x; 1.1121x over previous
#include <cuda_runtime.h>
#include <math.h>

#define N_NODESC 20000
#define N_EDGESC 120000
#define HY_STRIDE 44

// ---- static device scratch ----
__device__ int   g_deg[N_NODESC];
__device__ int   g_off[N_NODESC + 1];
__device__ int   g_cursor[N_NODESC];
__device__ int   g_sorted[N_EDGESC];             // permutation: sorted slot -> edge idx
__device__ float g_R[(size_t)N_NODESC * 384];    // R[n][j*24+u]
__device__ float g_hy[(size_t)N_EDGESC * HY_STRIDE + 16]; // per ORIGINAL edge: hv'[16], y[24], expv
__device__ float g_T[(size_t)N_NODESC * 384];    // T[n][t'], t'=u*16+j

#define C_EMB   8.4335730690754870f
#define C_V     0.05103103630798287f
#define C_LOGIT 0.003189439769248930f

__device__ __forceinline__ float susf(float v) {
    return (v > 0.f) ? __expf(-__fdividef(1.f, v)) : 0.f;
}
__device__ __forceinline__ float siluf(float z) {
    return __fdividef(z, 1.f + __expf(-z));
}

// ---------------- R GEMM (self-contained: computes MW per block) ----------------
// R[n][t] = sum_p x0[n][p] * MW[p][t],  MW[p][t] = sum_w M[p][w]*Wk2[j*384+u*16+w], t=j*24+u
#define RT_NODES 50
__global__ void k_R(const float* __restrict__ x, const float* __restrict__ Wq,
                    const float* __restrict__ Wdot, const float* __restrict__ Wk2) {
    __shared__ float sM[16][17];
    __shared__ float sW[16][385];
    __shared__ float sq[RT_NODES * 16];
    int t = threadIdx.x;  // 0..383

    if (t < 256) {
        int p = t >> 4, w = t & 15;
        float a = 0.f;
        #pragma unroll
        for (int r = 0; r < 16; r++) a += __ldg(&Wq[p * 16 + r]) * __ldg(&Wdot[r * 16 + w]);
        sM[p][w] = a * 0.25f * C_LOGIT;
    }
    __syncthreads();

    {
        int j = t / 24, u = t - j * 24;
        float wk[16];
        #pragma unroll
        for (int w = 0; w < 16; w++) wk[w] = __ldg(&Wk2[j * 384 + u * 16 + w]);
        #pragma unroll
        for (int p = 0; p < 16; p++) {
            float a = 0.f;
            #pragma unroll
            for (int w = 0; w < 16; w++) a += sM[p][w] * wk[w];
            sW[p][t] = a;
        }
    }

    int nb = blockIdx.x * RT_NODES;
    for (int i = t; i < RT_NODES * 16; i += 384) {
        int n = i >> 4, c = i & 15;
        sq[i] = x[(size_t)(nb + n) * 40 + c];
    }
    __syncthreads();

    float wr[16];
    #pragma unroll
    for (int p = 0; p < 16; p++) wr[p] = sW[p][t];

    float* Rp = g_R + (size_t)nb * 384 + t;
    #pragma unroll 2
    for (int n0 = 0; n0 < RT_NODES; n0++) {
        const float4* q4 = (const float4*)(sq + n0 * 16);
        float4 qa = q4[0], qb = q4[1], qc = q4[2], qdv = q4[3];
        float a = wr[0] * qa.x + wr[1] * qa.y + wr[2] * qa.z + wr[3] * qa.w
                + wr[4] * qb.x + wr[5] * qb.y + wr[6] * qb.z + wr[7] * qb.w
                + wr[8] * qc.x + wr[9] * qc.y + wr[10] * qc.z + wr[11] * qc.w
                + wr[12] * qdv.x + wr[13] * qdv.y + wr[14] * qdv.z + wr[15] * qdv.w;
        Rp[(size_t)n0 * 384] = a;
    }
}

__global__ void k_hist(const int* __restrict__ dst) {
    int i = blockIdx.x * blockDim.x + threadIdx.x;
    if (i < N_EDGESC) atomicAdd(&g_deg[dst[i]], 1);
}

__global__ void k_scan() {
    __shared__ int s[1024];
    int tid = threadIdx.x;
    const int CH = (N_NODESC + 1023) / 1024;  // 20
    int base = tid * CH;
    int sum = 0;
    #pragma unroll
    for (int c = 0; c < CH; c++) {
        int idx = base + c;
        if (idx < N_NODESC) sum += g_deg[idx];
    }
    s[tid] = sum;
    __syncthreads();
    for (int d = 1; d < 1024; d <<= 1) {
        int v = (tid >= d) ? s[tid - d] : 0;
        __syncthreads();
        s[tid] += v;
        __syncthreads();
    }
    int run = s[tid] - sum;
    for (int c = 0; c < CH; c++) {
        int idx = base + c;
        if (idx < N_NODESC) {
            g_off[idx] = run;
            g_cursor[idx] = run;
            run += g_deg[idx];
        }
    }
    if (tid == 1023) g_off[N_NODESC] = s[1023];
}

// ---------------- pass A: ORIGINAL edge order (no scatter dependency) ----------------
__global__ void k_passA(const float* __restrict__ x, const float* __restrict__ pos,
                        const float* __restrict__ Wk1, const float* __restrict__ Wv1,
                        const int* __restrict__ esrc, const int* __restrict__ edst) {
    __shared__ float s_wkv[320];
    {
        int tt = threadIdx.x;
        if (tt < 160) { s_wkv[tt] = __ldg(&Wk1[tt]); s_wkv[160 + tt] = __ldg(&Wv1[tt]); }
    }
    __syncthreads();

    int i = blockIdx.x * blockDim.x + threadIdx.x;
    if (i >= N_EDGESC) return;
    int s = esrc[i], d = edst[i];
    float* row = g_hy + (size_t)i * HY_STRIDE;

    float ev0 = pos[s * 3 + 0] - pos[d * 3 + 0];
    float ev1 = pos[s * 3 + 1] - pos[d * 3 + 1];
    float ev2 = pos[s * 3 + 2] - pos[d * 3 + 2];
    float elen = sqrtf(ev0 * ev0 + ev1 * ev1 + ev2 * ev2 + 1e-12f);

    float wcut = susf(10.f * (1.f - elen * 0.25f));
    if (!(wcut > 0.f)) {
        float4 z4 = make_float4(0.f, 0.f, 0.f, 0.f);
        ((float4*)row)[0] = z4; ((float4*)row)[1] = z4;
        ((float4*)row)[2] = z4; ((float4*)row)[3] = z4;
        ((float4*)row)[10] = z4;
        return;
    }

    float tt = elen * 2.75f;
    int b0 = (int)tt;
    float d0 = tt - (float)b0;
    float g0 = (b0 >= 1 && b0 <= 10) ? (C_EMB * susf(d0 + 1.f) * susf(1.f - d0)) : 0.f;
    float g1 = (b0 >= 0 && b0 <= 9)  ? (C_EMB * susf(d0) * susf(2.f - d0)) : 0.f;
    int r0 = b0 - 1; if (r0 < 0) r0 = 0; if (r0 > 9) r0 = 9;
    int r1 = b0;     if (r1 < 0) r1 = 0; if (r1 > 9) r1 = 9;

    float4 xr[10];
    const float4* xp4 = (const float4*)(x + (size_t)s * 40);
    #pragma unroll
    for (int q = 0; q < 10; q++) xr[q] = __ldg(&xp4[q]);
    const float* xf = (const float*)xr;

    float y[24];
    float rinv = __frcp_rn(elen);
    #pragma unroll
    for (int u = 0; u < 16; u++) y[u] = xf[u];
    #pragma unroll
    for (int u = 0; u < 8; u++)
        y[16 + u] = (xf[16 + u * 3] * ev0 + xf[17 + u * 3] * ev1 + xf[18 + u * 3] * ev2) * rinv;

    float lg = 0.f;
    const float4* Rp = (const float4*)(g_R + (size_t)d * 384);
    #pragma unroll
    for (int j = 0; j < 16; j++) {
        float zk = g0 * s_wkv[r0 * 16 + j] + g1 * s_wkv[r1 * 16 + j];
        float hk = siluf(zk);
        float Sj = 0.f;
        #pragma unroll
        for (int q4 = 0; q4 < 6; q4++) {
            float4 r4 = __ldg(&Rp[j * 6 + q4]);
            Sj += r4.x * y[q4 * 4 + 0] + r4.y * y[q4 * 4 + 1]
                + r4.z * y[q4 * 4 + 2] + r4.w * y[q4 * 4 + 3];
        }
        lg += hk * Sj;
    }
    float expv = wcut * __expf(lg);
    float sev = sqrtf(expv);

    #pragma unroll
    for (int j4 = 0; j4 < 4; j4++) {
        float h0 = sev * siluf(g0 * s_wkv[160 + r0 * 16 + j4 * 4 + 0] + g1 * s_wkv[160 + r1 * 16 + j4 * 4 + 0]);
        float h1 = sev * siluf(g0 * s_wkv[160 + r0 * 16 + j4 * 4 + 1] + g1 * s_wkv[160 + r1 * 16 + j4 * 4 + 1]);
        float h2 = sev * siluf(g0 * s_wkv[160 + r0 * 16 + j4 * 4 + 2] + g1 * s_wkv[160 + r1 * 16 + j4 * 4 + 2]);
        float h3 = sev * siluf(g0 * s_wkv[160 + r0 * 16 + j4 * 4 + 3] + g1 * s_wkv[160 + r1 * 16 + j4 * 4 + 3]);
        ((float4*)row)[j4] = make_float4(h0, h1, h2, h3);
    }
    #pragma unroll
    for (int q4 = 0; q4 < 6; q4++)
        ((float4*)(row + 16))[q4] = make_float4(y[q4 * 4 + 0], y[q4 * 4 + 1],
                                                y[q4 * 4 + 2], y[q4 * 4 + 3]);
    ((float4*)row)[10] = make_float4(expv, 0.f, 0.f, 0.f);
}

__global__ void k_scatter(const int* __restrict__ dst) {
    int i = blockIdx.x * blockDim.x + threadIdx.x;
    if (i < N_EDGESC) {
        int d = dst[i];
        int p = atomicAdd(&g_cursor[d], 1);
        g_sorted[p] = i;
    }
}

// ---------------- pass B: warp per node, software-pipelined ----------------
__global__ void k_passB() {
    int wwarp = threadIdx.x >> 5;
    int l = threadIdx.x & 31;
    int n = blockIdx.x * 16 + wwarp;   // 512 threads = 16 warps
    if (n >= N_NODESC) return;
    int beg = g_off[n], end = g_off[n + 1];

    float acc[12];
    #pragma unroll
    for (int k = 0; k < 12; k++) acc[k] = 0.f;
    float z = 0.f;
    int par = l >> 4;
    int jj = l & 15;

    if (beg < end) {
        int e = g_sorted[beg];
        const float* row = g_hy + (size_t)e * HY_STRIDE;
        float A = row[l];
        float B = (l < 16) ? row[32 + l] : 0.f;

        for (int i = beg; i < end; i++) {
            float A2 = 0.f, B2 = 0.f;
            if (i + 1 < end) {           // prefetch next edge's row
                int e2 = g_sorted[i + 1];
                const float* row2 = g_hy + (size_t)e2 * HY_STRIDE;
                A2 = row2[l];
                B2 = (l < 16) ? row2[32 + l] : 0.f;
            }
            z += __shfl_sync(0xffffffffu, B, 8);
            float hval = __shfl_sync(0xffffffffu, A, jj);
            #pragma unroll
            for (int k = 0; k < 8; k++) {
                float yv = __shfl_sync(0xffffffffu, A, 16 + par + 2 * k);
                acc[k] += hval * yv;
            }
            #pragma unroll
            for (int k = 8; k < 12; k++) {
                float yv = __shfl_sync(0xffffffffu, B, par + 2 * k - 16);
                acc[k] += hval * yv;
            }
            A = A2; B = B2;
        }
    }

    if (z == 0.f) z = 1.f;
    float sc = rsqrtf(z);
    float* Tp = g_T + (size_t)n * 384;
    #pragma unroll
    for (int k = 0; k < 12; k++) Tp[l + 32 * k] = acc[k] * sc;
}

// ---------------- output GEMM: out = C_V * T @ W' ----------------
__global__ void k_out(const float* __restrict__ Wv2, float* __restrict__ out) {
    __shared__ __align__(16) float sW[32][36];
    __shared__ __align__(16) float sT[128][36];
    int t = threadIdx.x;                // 256
    int base = blockIdx.x * 128;
    int c0 = t & 15;
    int g = t >> 4;

    float acc[8][2];
    #pragma unroll
    for (int i2 = 0; i2 < 8; i2++) { acc[i2][0] = 0.f; acc[i2][1] = 0.f; }

    for (int kc = 0; kc < 12; kc++) {
        __syncthreads();
        #pragma unroll
        for (int q = 0; q < 4; q++) {
            int i = q * 256 + t;
            int kkl = i >> 5, col = i & 31;
            int k = kc * 32 + kkl;
            sW[col][kkl] = __ldg(&Wv2[(k & 15) * 768 + (k >> 4) * 32 + col]);
        }
        #pragma unroll
        for (int q = 0; q < 16; q++) {
            int i = q * 256 + t;
            int node = i >> 5, kkl = i & 31;
            int n = base + node;
            sT[node][kkl] = (n < N_NODESC) ? g_T[(size_t)n * 384 + kc * 32 + kkl] : 0.f;
        }
        __syncthreads();
        #pragma unroll
        for (int kk4 = 0; kk4 < 8; kk4++) {
            float4 w0 = ((const float4*)sW[c0])[kk4];
            float4 w1 = ((const float4*)sW[c0 + 16])[kk4];
            #pragma unroll
            for (int i2 = 0; i2 < 8; i2++) {
                float4 tv = ((const float4*)sT[g * 8 + i2])[kk4];
                acc[i2][0] += tv.x * w0.x + tv.y * w0.y + tv.z * w0.z + tv.w * w0.w;
                acc[i2][1] += tv.x * w1.x + tv.y * w1.y + tv.z * w1.z + tv.w * w1.w;
            }
        }
    }
    #pragma unroll
    for (int i2 = 0; i2 < 8; i2++) {
        int n = base + g * 8 + i2;
        if (n < N_NODESC) {
            out[n * 32 + c0]      = acc[i2][0] * C_V;
            out[n * 32 + c0 + 16] = acc[i2][1] * C_V;
        }
    }
}

// ---------------- launch ----------------
extern "C" void kernel_launch(void* const* d_in, const int* in_sizes, int n_in,
                              void* d_out, int out_size) {
    (void)in_sizes; (void)n_in; (void)out_size;
    const float* x    = (const float*)d_in[0];
    const float* pos  = (const float*)d_in[1];
    const float* Wq   = (const float*)d_in[2];
    const float* Wk1  = (const float*)d_in[3];
    const float* Wk2  = (const float*)d_in[4];
    const float* Wv1  = (const float*)d_in[5];
    const float* Wv2  = (const float*)d_in[6];
    const float* Wdot = (const float*)d_in[7];
    const int* esrc   = (const int*)d_in[8];
    const int* edst   = (const int*)d_in[9];
    float* out = (float*)d_out;

    void* degp = nullptr;
    cudaGetSymbolAddress(&degp, g_deg);
    cudaMemsetAsync(degp, 0, N_NODESC * sizeof(int));

    k_R<<<N_NODESC / RT_NODES, 384>>>(x, Wq, Wdot, Wk2);       // kernel 1
    k_hist<<<(N_EDGESC + 255) / 256, 256>>>(edst);             // kernel 2
    k_scan<<<1, 1024>>>();                                     // kernel 3
    k_passA<<<(N_EDGESC + 255) / 256, 256>>>(x, pos, Wk1, Wv1, esrc, edst); // kernel 4 (profiled)
    k_scatter<<<(N_EDGESC + 255) / 256, 256>>>(edst);          // kernel 5
    k_passB<<<(N_NODESC + 15) / 16, 512>>>();                  // kernel 6
    k_out<<<(N_NODESC + 127) / 128, 256>>>(Wv2, out);          // kernel 7
}

// round 9
// speedup vs baseline: 1.6575x; 1.2202x over previous
#include <cuda_runtime.h>
#include <math.h>

#define N_NODESC 20000
#define N_EDGESC 120000
#define HY_STRIDE 44

// ---- static device scratch ----
__device__ int   g_deg[N_NODESC];
__device__ int   g_off[N_NODESC + 1];
__device__ int   g_cursor[N_NODESC];
__device__ int2  g_edge[N_EDGESC];               // sorted (src,dst)
__device__ float g_R[(size_t)N_NODESC * 384];    // R[n][j*24+u]
__device__ float g_hy[(size_t)N_EDGESC * HY_STRIDE + 16]; // per SORTED slot: hv'[16], y[24], expv
__device__ float g_T[(size_t)N_NODESC * 384];    // T[n][t'], t'=u*16+j

#define C_EMB   8.4335730690754870f
#define C_V     0.05103103630798287f
#define C_LOGIT 0.003189439769248930f

__device__ __forceinline__ float susf(float v) {
    return (v > 0.f) ? __expf(-__fdividef(1.f, v)) : 0.f;
}
__device__ __forceinline__ float siluf(float z) {
    return __fdividef(z, 1.f + __expf(-z));
}

__global__ void k_hist(const int* __restrict__ dst) {
    int i = blockIdx.x * blockDim.x + threadIdx.x;
    if (i < N_EDGESC) atomicAdd(&g_deg[dst[i]], 1);
}

__global__ void k_scan() {
    __shared__ int s[1024];
    int tid = threadIdx.x;
    const int CH = (N_NODESC + 1023) / 1024;  // 20
    int base = tid * CH;
    int sum = 0;
    #pragma unroll
    for (int c = 0; c < CH; c++) {
        int idx = base + c;
        if (idx < N_NODESC) sum += g_deg[idx];
    }
    s[tid] = sum;
    __syncthreads();
    for (int d = 1; d < 1024; d <<= 1) {
        int v = (tid >= d) ? s[tid - d] : 0;
        __syncthreads();
        s[tid] += v;
        __syncthreads();
    }
    int run = s[tid] - sum;
    for (int c = 0; c < CH; c++) {
        int idx = base + c;
        if (idx < N_NODESC) {
            g_off[idx] = run;
            g_cursor[idx] = run;
            run += g_deg[idx];
        }
    }
    if (tid == 1023) g_off[N_NODESC] = s[1023];
}

__global__ void k_scatter(const int* __restrict__ src, const int* __restrict__ dst) {
    int i = blockIdx.x * blockDim.x + threadIdx.x;
    if (i < N_EDGESC) {
        int d = dst[i];
        int p = atomicAdd(&g_cursor[d], 1);
        g_edge[p] = make_int2(src[i], d);
    }
}

// ---------------- R GEMM (self-contained: computes MW per block) ----------------
// R[n][t] = sum_p x0[n][p]*MW[p][t],  MW[p][t] = sum_w M[p][w]*Wk2[j*384+u*16+w], t=j*24+u
#define RT_NODES 50
__global__ void k_R(const float* __restrict__ x, const float* __restrict__ Wq,
                    const float* __restrict__ Wdot, const float* __restrict__ Wk2) {
    __shared__ float sM[16][17];
    __shared__ float sW[16][385];
    __shared__ float sq[RT_NODES * 16];
    int t = threadIdx.x;  // 0..383

    if (t < 256) {
        int p = t >> 4, w = t & 15;
        float a = 0.f;
        #pragma unroll
        for (int r = 0; r < 16; r++) a += __ldg(&Wq[p * 16 + r]) * __ldg(&Wdot[r * 16 + w]);
        sM[p][w] = a * 0.25f * C_LOGIT;
    }
    __syncthreads();

    {
        int j = t / 24, u = t - j * 24;
        float wk[16];
        #pragma unroll
        for (int w = 0; w < 16; w++) wk[w] = __ldg(&Wk2[j * 384 + u * 16 + w]);
        #pragma unroll
        for (int p = 0; p < 16; p++) {
            float a = 0.f;
            #pragma unroll
            for (int w = 0; w < 16; w++) a += sM[p][w] * wk[w];
            sW[p][t] = a;
        }
    }

    int nb = blockIdx.x * RT_NODES;
    for (int i = t; i < RT_NODES * 16; i += 384) {
        int n = i >> 4, c = i & 15;
        sq[i] = x[(size_t)(nb + n) * 40 + c];
    }
    __syncthreads();

    float wr[16];
    #pragma unroll
    for (int p = 0; p < 16; p++) wr[p] = sW[p][t];

    float* Rp = g_R + (size_t)nb * 384 + t;
    #pragma unroll 2
    for (int n0 = 0; n0 < RT_NODES; n0++) {
        const float4* q4 = (const float4*)(sq + n0 * 16);
        float4 qa = q4[0], qb = q4[1], qc = q4[2], qdv = q4[3];
        float a = wr[0] * qa.x + wr[1] * qa.y + wr[2] * qa.z + wr[3] * qa.w
                + wr[4] * qb.x + wr[5] * qb.y + wr[6] * qb.z + wr[7] * qb.w
                + wr[8] * qc.x + wr[9] * qc.y + wr[10] * qc.z + wr[11] * qc.w
                + wr[12] * qdv.x + wr[13] * qdv.y + wr[14] * qdv.z + wr[15] * qdv.w;
        Rp[(size_t)n0 * 384] = a;
    }
}

// ---------------- pass A: SORTED edge order (R-row L1 broadcast locality) ----------------
__global__ void k_passA(const float* __restrict__ x, const float* __restrict__ pos,
                        const float* __restrict__ Wk1, const float* __restrict__ Wv1) {
    __shared__ float s_wkv[320];
    {
        int tt = threadIdx.x;
        if (tt < 160) { s_wkv[tt] = __ldg(&Wk1[tt]); s_wkv[160 + tt] = __ldg(&Wv1[tt]); }
    }
    __syncthreads();

    int i = blockIdx.x * blockDim.x + threadIdx.x;
    if (i >= N_EDGESC) return;
    int2 sd = g_edge[i];
    int s = sd.x, d = sd.y;
    float* row = g_hy + (size_t)i * HY_STRIDE;

    float ev0 = pos[s * 3 + 0] - pos[d * 3 + 0];
    float ev1 = pos[s * 3 + 1] - pos[d * 3 + 1];
    float ev2 = pos[s * 3 + 2] - pos[d * 3 + 2];
    float elen = sqrtf(ev0 * ev0 + ev1 * ev1 + ev2 * ev2 + 1e-12f);

    float wcut = susf(10.f * (1.f - elen * 0.25f));
    if (!(wcut > 0.f)) {
        float4 z4 = make_float4(0.f, 0.f, 0.f, 0.f);
        ((float4*)row)[0] = z4; ((float4*)row)[1] = z4;
        ((float4*)row)[2] = z4; ((float4*)row)[3] = z4;
        ((float4*)row)[10] = z4;
        return;
    }

    float tt = elen * 2.75f;
    int b0 = (int)tt;
    float d0 = tt - (float)b0;
    float g0 = (b0 >= 1 && b0 <= 10) ? (C_EMB * susf(d0 + 1.f) * susf(1.f - d0)) : 0.f;
    float g1 = (b0 >= 0 && b0 <= 9)  ? (C_EMB * susf(d0) * susf(2.f - d0)) : 0.f;
    int r0 = b0 - 1; if (r0 < 0) r0 = 0; if (r0 > 9) r0 = 9;
    int r1 = b0;     if (r1 < 0) r1 = 0; if (r1 > 9) r1 = 9;

    float4 xr[10];
    const float4* xp4 = (const float4*)(x + (size_t)s * 40);
    #pragma unroll
    for (int q = 0; q < 10; q++) xr[q] = __ldg(&xp4[q]);
    const float* xf = (const float*)xr;

    float y[24];
    float rinv = __frcp_rn(elen);
    #pragma unroll
    for (int u = 0; u < 16; u++) y[u] = xf[u];
    #pragma unroll
    for (int u = 0; u < 8; u++)
        y[16 + u] = (xf[16 + u * 3] * ev0 + xf[17 + u * 3] * ev1 + xf[18 + u * 3] * ev2) * rinv;

    float lg = 0.f;
    const float4* Rp = (const float4*)(g_R + (size_t)d * 384);
    #pragma unroll
    for (int j = 0; j < 16; j++) {
        float zk = g0 * s_wkv[r0 * 16 + j] + g1 * s_wkv[r1 * 16 + j];
        float hk = siluf(zk);
        float Sj = 0.f;
        #pragma unroll
        for (int q4 = 0; q4 < 6; q4++) {
            float4 r4 = __ldg(&Rp[j * 6 + q4]);
            Sj += r4.x * y[q4 * 4 + 0] + r4.y * y[q4 * 4 + 1]
                + r4.z * y[q4 * 4 + 2] + r4.w * y[q4 * 4 + 3];
        }
        lg += hk * Sj;
    }
    float expv = wcut * __expf(lg);
    float sev = sqrtf(expv);

    #pragma unroll
    for (int j4 = 0; j4 < 4; j4++) {
        float h0 = sev * siluf(g0 * s_wkv[160 + r0 * 16 + j4 * 4 + 0] + g1 * s_wkv[160 + r1 * 16 + j4 * 4 + 0]);
        float h1 = sev * siluf(g0 * s_wkv[160 + r0 * 16 + j4 * 4 + 1] + g1 * s_wkv[160 + r1 * 16 + j4 * 4 + 1]);
        float h2 = sev * siluf(g0 * s_wkv[160 + r0 * 16 + j4 * 4 + 2] + g1 * s_wkv[160 + r1 * 16 + j4 * 4 + 2]);
        float h3 = sev * siluf(g0 * s_wkv[160 + r0 * 16 + j4 * 4 + 3] + g1 * s_wkv[160 + r1 * 16 + j4 * 4 + 3]);
        ((float4*)row)[j4] = make_float4(h0, h1, h2, h3);
    }
    #pragma unroll
    for (int q4 = 0; q4 < 6; q4++)
        ((float4*)(row + 16))[q4] = make_float4(y[q4 * 4 + 0], y[q4 * 4 + 1],
                                                y[q4 * 4 + 2], y[q4 * 4 + 3]);
    ((float4*)row)[10] = make_float4(expv, 0.f, 0.f, 0.f);
}

// ---------------- pass B: warp per node, contiguous rows, pipelined ----------------
__global__ void k_passB() {
    int wwarp = threadIdx.x >> 5;
    int l = threadIdx.x & 31;
    int n = blockIdx.x * 16 + wwarp;   // 512 threads = 16 warps
    if (n >= N_NODESC) return;
    int beg = g_off[n], end = g_off[n + 1];

    float acc[12];
    #pragma unroll
    for (int k = 0; k < 12; k++) acc[k] = 0.f;
    float z = 0.f;
    int par = l >> 4;
    int jj = l & 15;

    if (beg < end) {
        const float* row = g_hy + (size_t)beg * HY_STRIDE;
        float A = row[l];
        float B = (l < 16) ? row[32 + l] : 0.f;

        for (int i = beg; i < end; i++) {
            float A2 = 0.f, B2 = 0.f;
            if (i + 1 < end) {
                const float* row2 = g_hy + (size_t)(i + 1) * HY_STRIDE;
                A2 = row2[l];
                B2 = (l < 16) ? row2[32 + l] : 0.f;
            }
            z += __shfl_sync(0xffffffffu, B, 8);
            float hval = __shfl_sync(0xffffffffu, A, jj);
            #pragma unroll
            for (int k = 0; k < 8; k++) {
                float yv = __shfl_sync(0xffffffffu, A, 16 + par + 2 * k);
                acc[k] += hval * yv;
            }
            #pragma unroll
            for (int k = 8; k < 12; k++) {
                float yv = __shfl_sync(0xffffffffu, B, par + 2 * k - 16);
                acc[k] += hval * yv;
            }
            A = A2; B = B2;
        }
    }

    if (z == 0.f) z = 1.f;
    float sc = rsqrtf(z);
    float* Tp = g_T + (size_t)n * 384;
    #pragma unroll
    for (int k = 0; k < 12; k++) Tp[l + 32 * k] = acc[k] * sc;
}

// ---------------- output GEMM: out = C_V * T @ W' ----------------
__global__ void k_out(const float* __restrict__ Wv2, float* __restrict__ out) {
    __shared__ __align__(16) float sW[32][36];
    __shared__ __align__(16) float sT[128][36];
    int t = threadIdx.x;                // 256
    int base = blockIdx.x * 128;
    int c0 = t & 15;
    int g = t >> 4;

    float acc[8][2];
    #pragma unroll
    for (int i2 = 0; i2 < 8; i2++) { acc[i2][0] = 0.f; acc[i2][1] = 0.f; }

    for (int kc = 0; kc < 12; kc++) {
        __syncthreads();
        #pragma unroll
        for (int q = 0; q < 4; q++) {
            int i = q * 256 + t;
            int kkl = i >> 5, col = i & 31;
            int k = kc * 32 + kkl;
            sW[col][kkl] = __ldg(&Wv2[(k & 15) * 768 + (k >> 4) * 32 + col]);
        }
        #pragma unroll
        for (int q = 0; q < 16; q++) {
            int i = q * 256 + t;
            int node = i >> 5, kkl = i & 31;
            int n = base + node;
            sT[node][kkl] = (n < N_NODESC) ? g_T[(size_t)n * 384 + kc * 32 + kkl] : 0.f;
        }
        __syncthreads();
        #pragma unroll
        for (int kk4 = 0; kk4 < 8; kk4++) {
            float4 w0 = ((const float4*)sW[c0])[kk4];
            float4 w1 = ((const float4*)sW[c0 + 16])[kk4];
            #pragma unroll
            for (int i2 = 0; i2 < 8; i2++) {
                float4 tv = ((const float4*)sT[g * 8 + i2])[kk4];
                acc[i2][0] += tv.x * w0.x + tv.y * w0.y + tv.z * w0.z + tv.w * w0.w;
                acc[i2][1] += tv.x * w1.x + tv.y * w1.y + tv.z * w1.z + tv.w * w1.w;
            }
        }
    }
    #pragma unroll
    for (int i2 = 0; i2 < 8; i2++) {
        int n = base + g * 8 + i2;
        if (n < N_NODESC) {
            out[n * 32 + c0]      = acc[i2][0] * C_V;
            out[n * 32 + c0 + 16] = acc[i2][1] * C_V;
        }
    }
}

// ---------------- launch ----------------
extern "C" void kernel_launch(void* const* d_in, const int* in_sizes, int n_in,
                              void* d_out, int out_size) {
    (void)in_sizes; (void)n_in; (void)out_size;
    const float* x    = (const float*)d_in[0];
    const float* pos  = (const float*)d_in[1];
    const float* Wq   = (const float*)d_in[2];
    const float* Wk1  = (const float*)d_in[3];
    const float* Wk2  = (const float*)d_in[4];
    const float* Wv1  = (const float*)d_in[5];
    const float* Wv2  = (const float*)d_in[6];
    const float* Wdot = (const float*)d_in[7];
    const int* esrc   = (const int*)d_in[8];
    const int* edst   = (const int*)d_in[9];
    float* out = (float*)d_out;

    void* degp = nullptr;
    cudaGetSymbolAddress(&degp, g_deg);
    cudaMemsetAsync(degp, 0, N_NODESC * sizeof(int));

    k_hist<<<(N_EDGESC + 255) / 256, 256>>>(edst);                 // 1
    k_scan<<<1, 1024>>>();                                         // 2
    k_scatter<<<(N_EDGESC + 255) / 256, 256>>>(esrc, edst);        // 3
    k_R<<<N_NODESC / RT_NODES, 384>>>(x, Wq, Wdot, Wk2);           // 4 (profiled)
    k_passA<<<(N_EDGESC + 255) / 256, 256>>>(x, pos, Wk1, Wv1);    // 5
    k_passB<<<(N_NODESC + 15) / 16, 512>>>();                      // 6
    k_out<<<(N_NODESC + 127) / 128, 256>>>(Wv2, out);              // 7
}

// round 11
// speedup vs baseline: 1.7753x; 1.0711x over previous
#include <cuda_runtime.h>
#include <math.h>

#define N_NODESC 20000
#define N_EDGESC 120000
#define HY_STRIDE 44

// ---- static device scratch (zero-initialized at module load) ----
__device__ int   g_deg[N_NODESC];     // zero invariant restored by k_scatter each run
__device__ int   g_off[N_NODESC + 1];
__device__ int   g_cursor[N_NODESC];
__device__ int2  g_edge[N_EDGESC];               // sorted (src,dst)
__device__ float g_R[(size_t)N_NODESC * 384];    // R[n][j*24+u]
__device__ float g_hy[(size_t)N_EDGESC * HY_STRIDE + 16]; // per SORTED slot: hv'[16], y[24], expv

#define C_EMB   8.4335730690754870f
#define C_V     0.05103103630798287f
#define C_LOGIT 0.003189439769248930f

__device__ __forceinline__ float susf(float v) {
    return (v > 0.f) ? __expf(-__fdividef(1.f, v)) : 0.f;
}
__device__ __forceinline__ float siluf(float z) {
    return __fdividef(z, 1.f + __expf(-z));
}

__global__ void k_hist(const int* __restrict__ dst) {
    int i = blockIdx.x * blockDim.x + threadIdx.x;
    if (i < N_EDGESC) atomicAdd(&g_deg[dst[i]], 1);
}

__global__ void k_scan() {
    __shared__ int s[1024];
    int tid = threadIdx.x;
    const int CH = (N_NODESC + 1023) / 1024;  // 20
    int base = tid * CH;
    int sum = 0;
    #pragma unroll
    for (int c = 0; c < CH; c++) {
        int idx = base + c;
        if (idx < N_NODESC) sum += g_deg[idx];
    }
    s[tid] = sum;
    __syncthreads();
    for (int d = 1; d < 1024; d <<= 1) {
        int v = (tid >= d) ? s[tid - d] : 0;
        __syncthreads();
        s[tid] += v;
        __syncthreads();
    }
    int run = s[tid] - sum;
    for (int c = 0; c < CH; c++) {
        int idx = base + c;
        if (idx < N_NODESC) {
            g_off[idx] = run;
            g_cursor[idx] = run;
            run += g_deg[idx];
        }
    }
    if (tid == 1023) g_off[N_NODESC] = s[1023];
}

// scatter + re-zero g_deg (g_deg already consumed by k_scan; restores the
// zero invariant for the next graph replay)
__global__ void k_scatter(const int* __restrict__ src, const int* __restrict__ dst) {
    int i = blockIdx.x * blockDim.x + threadIdx.x;
    if (i < N_EDGESC) {
        int d = dst[i];
        int p = atomicAdd(&g_cursor[d], 1);
        g_edge[p] = make_int2(src[i], d);
        if (i < N_NODESC) g_deg[i] = 0;
    }
}

// ---------------- R GEMM (computes MW per block) ----------------
// R[n][t] = sum_p x0[n][p]*MW[p][t],  MW[p][t] = sum_w M[p][w]*Wk2[j*384+u*16+w], t=j*24+u
#define RT_NODES 100
__global__ void k_R(const float* __restrict__ x, const float* __restrict__ Wq,
                    const float* __restrict__ Wdot, const float* __restrict__ Wk2) {
    __shared__ float sM[16][17];
    __shared__ float sW[16][385];
    __shared__ float sq[RT_NODES * 16];
    int t = threadIdx.x;  // 0..383

    if (t < 256) {
        int p = t >> 4, w = t & 15;
        float a = 0.f;
        #pragma unroll
        for (int r = 0; r < 16; r++) a += __ldg(&Wq[p * 16 + r]) * __ldg(&Wdot[r * 16 + w]);
        sM[p][w] = a * 0.25f * C_LOGIT;
    }
    __syncthreads();

    {
        int j = t / 24, u = t - j * 24;
        float wk[16];
        #pragma unroll
        for (int w = 0; w < 16; w++) wk[w] = __ldg(&Wk2[j * 384 + u * 16 + w]);
        #pragma unroll
        for (int p = 0; p < 16; p++) {
            float a = 0.f;
            #pragma unroll
            for (int w = 0; w < 16; w++) a += sM[p][w] * wk[w];
            sW[p][t] = a;
        }
    }

    int nb = blockIdx.x * RT_NODES;
    for (int i = t; i < RT_NODES * 16; i += 384) {
        int n = i >> 4, c = i & 15;
        sq[i] = x[(size_t)(nb + n) * 40 + c];
    }
    __syncthreads();

    float wr[16];
    #pragma unroll
    for (int p = 0; p < 16; p++) wr[p] = sW[p][t];

    float* Rp = g_R + (size_t)nb * 384 + t;
    #pragma unroll 2
    for (int n0 = 0; n0 < RT_NODES; n0++) {
        const float4* q4 = (const float4*)(sq + n0 * 16);
        float4 qa = q4[0], qb = q4[1], qc = q4[2], qdv = q4[3];
        float a = wr[0] * qa.x + wr[1] * qa.y + wr[2] * qa.z + wr[3] * qa.w
                + wr[4] * qb.x + wr[5] * qb.y + wr[6] * qb.z + wr[7] * qb.w
                + wr[8] * qc.x + wr[9] * qc.y + wr[10] * qc.z + wr[11] * qc.w
                + wr[12] * qdv.x + wr[13] * qdv.y + wr[14] * qdv.z + wr[15] * qdv.w;
        Rp[(size_t)n0 * 384] = a;
    }
}

// ---------------- pass A: SORTED edge order (R-row L1 broadcast locality) ----------------
__global__ void k_passA(const float* __restrict__ x, const float* __restrict__ pos,
                        const float* __restrict__ Wk1, const float* __restrict__ Wv1) {
    __shared__ float s_wkv[320];
    {
        int tt = threadIdx.x;
        if (tt < 160) { s_wkv[tt] = __ldg(&Wk1[tt]); s_wkv[160 + tt] = __ldg(&Wv1[tt]); }
    }
    __syncthreads();

    int i = blockIdx.x * blockDim.x + threadIdx.x;
    if (i >= N_EDGESC) return;
    int2 sd = g_edge[i];
    int s = sd.x, d = sd.y;
    float* row = g_hy + (size_t)i * HY_STRIDE;

    float ev0 = pos[s * 3 + 0] - pos[d * 3 + 0];
    float ev1 = pos[s * 3 + 1] - pos[d * 3 + 1];
    float ev2 = pos[s * 3 + 2] - pos[d * 3 + 2];
    float elen = sqrtf(ev0 * ev0 + ev1 * ev1 + ev2 * ev2 + 1e-12f);

    float wcut = susf(10.f * (1.f - elen * 0.25f));
    if (!(wcut > 0.f)) {
        float4 z4 = make_float4(0.f, 0.f, 0.f, 0.f);
        ((float4*)row)[0] = z4; ((float4*)row)[1] = z4;
        ((float4*)row)[2] = z4; ((float4*)row)[3] = z4;
        ((float4*)row)[10] = z4;
        return;
    }

    float tt = elen * 2.75f;
    int b0 = (int)tt;
    float d0 = tt - (float)b0;
    float g0 = (b0 >= 1 && b0 <= 10) ? (C_EMB * susf(d0 + 1.f) * susf(1.f - d0)) : 0.f;
    float g1 = (b0 >= 0 && b0 <= 9)  ? (C_EMB * susf(d0) * susf(2.f - d0)) : 0.f;
    int r0 = b0 - 1; if (r0 < 0) r0 = 0; if (r0 > 9) r0 = 9;
    int r1 = b0;     if (r1 < 0) r1 = 0; if (r1 > 9) r1 = 9;

    float4 xr[10];
    const float4* xp4 = (const float4*)(x + (size_t)s * 40);
    #pragma unroll
    for (int q = 0; q < 10; q++) xr[q] = __ldg(&xp4[q]);
    const float* xf = (const float*)xr;

    float y[24];
    float rinv = __frcp_rn(elen);
    #pragma unroll
    for (int u = 0; u < 16; u++) y[u] = xf[u];
    #pragma unroll
    for (int u = 0; u < 8; u++)
        y[16 + u] = (xf[16 + u * 3] * ev0 + xf[17 + u * 3] * ev1 + xf[18 + u * 3] * ev2) * rinv;

    float lg = 0.f;
    const float4* Rp = (const float4*)(g_R + (size_t)d * 384);
    #pragma unroll
    for (int j = 0; j < 16; j++) {
        float zk = g0 * s_wkv[r0 * 16 + j] + g1 * s_wkv[r1 * 16 + j];
        float hk = siluf(zk);
        float Sj = 0.f;
        #pragma unroll
        for (int q4 = 0; q4 < 6; q4++) {
            float4 r4 = __ldg(&Rp[j * 6 + q4]);
            Sj += r4.x * y[q4 * 4 + 0] + r4.y * y[q4 * 4 + 1]
                + r4.z * y[q4 * 4 + 2] + r4.w * y[q4 * 4 + 3];
        }
        lg += hk * Sj;
    }
    float expv = wcut * __expf(lg);
    float sev = sqrtf(expv);

    #pragma unroll
    for (int j4 = 0; j4 < 4; j4++) {
        float h0 = sev * siluf(g0 * s_wkv[160 + r0 * 16 + j4 * 4 + 0] + g1 * s_wkv[160 + r1 * 16 + j4 * 4 + 0]);
        float h1 = sev * siluf(g0 * s_wkv[160 + r0 * 16 + j4 * 4 + 1] + g1 * s_wkv[160 + r1 * 16 + j4 * 4 + 1]);
        float h2 = sev * siluf(g0 * s_wkv[160 + r0 * 16 + j4 * 4 + 2] + g1 * s_wkv[160 + r1 * 16 + j4 * 4 + 2]);
        float h3 = sev * siluf(g0 * s_wkv[160 + r0 * 16 + j4 * 4 + 3] + g1 * s_wkv[160 + r1 * 16 + j4 * 4 + 3]);
        ((float4*)row)[j4] = make_float4(h0, h1, h2, h3);
    }
    #pragma unroll
    for (int q4 = 0; q4 < 6; q4++)
        ((float4*)(row + 16))[q4] = make_float4(y[q4 * 4 + 0], y[q4 * 4 + 1],
                                                y[q4 * 4 + 2], y[q4 * 4 + 3]);
    ((float4*)row)[10] = make_float4(expv, 0.f, 0.f, 0.f);
}

// ---------------- fused pass B + output GEMM ----------------
// Block: 448 threads = 14 warps, 28 nodes (2 per warp).
// Phase 1 (passB): warp accumulates T rows for its 2 nodes into smem sT.
// Phase 2 (GEMM):  out[n][col] = C_V * sum_t sT[n][t] * W'[t][col].
#define BN 28
__global__ void __launch_bounds__(448)
k_passBout(const float* __restrict__ Wv2, float* __restrict__ out) {
    __shared__ float sT[BN][384];     // 43,008 B
    __shared__ float sWt[32][34];     // [k_local][col], pad 2 -> conflict-free

    int t = threadIdx.x;
    int l = t & 31, w = t >> 5;       // warp 0..13
    int base = blockIdx.x * BN;
    int par = l >> 4;
    int jj = l & 15;

    // ---- phase 1: passB ----
    #pragma unroll
    for (int q = 0; q < 2; q++) {
        int n = base + w * 2 + q;
        float acc[12];
        #pragma unroll
        for (int k = 0; k < 12; k++) acc[k] = 0.f;
        float z = 0.f;

        if (n < N_NODESC) {
            int beg = g_off[n], end = g_off[n + 1];
            if (beg < end) {
                const float* row = g_hy + (size_t)beg * HY_STRIDE;
                float A = row[l];
                float B = (l < 16) ? row[32 + l] : 0.f;
                for (int i = beg; i < end; i++) {
                    float A2 = 0.f, B2 = 0.f;
                    if (i + 1 < end) {
                        const float* row2 = g_hy + (size_t)(i + 1) * HY_STRIDE;
                        A2 = row2[l];
                        B2 = (l < 16) ? row2[32 + l] : 0.f;
                    }
                    z += __shfl_sync(0xffffffffu, B, 8);
                    float hval = __shfl_sync(0xffffffffu, A, jj);
                    #pragma unroll
                    for (int k = 0; k < 8; k++) {
                        float yv = __shfl_sync(0xffffffffu, A, 16 + par + 2 * k);
                        acc[k] += hval * yv;
                    }
                    #pragma unroll
                    for (int k = 8; k < 12; k++) {
                        float yv = __shfl_sync(0xffffffffu, B, par + 2 * k - 16);
                        acc[k] += hval * yv;
                    }
                    A = A2; B = B2;
                }
            }
        }
        if (z == 0.f) z = 1.f;
        float sc = rsqrtf(z);
        #pragma unroll
        for (int k = 0; k < 12; k++) sT[w * 2 + q][l + 32 * k] = acc[k] * sc;
    }
    __syncthreads();

    // ---- phase 2: GEMM out = C_V * sT @ W' ----
    // thread -> col c0 = l, node pair g = w (nodes g*2, g*2+1)
    float acc0 = 0.f, acc1 = 0.f;
    const float* r0 = sT[w * 2];
    const float* r1 = sT[w * 2 + 1];
    for (int kc = 0; kc < 12; kc++) {
        // stage W chunk transposed: global t'-index k = kc*32+kk
        for (int i = t; i < 1024; i += 448) {
            int kk = i >> 5, col = i & 31;
            int k = kc * 32 + kk;
            sWt[kk][col] = __ldg(&Wv2[(k & 15) * 768 + (k >> 4) * 32 + col]);
        }
        __syncthreads();
        #pragma unroll 8
        for (int kk = 0; kk < 32; kk++) {
            float wv = sWt[kk][l];
            float t0 = r0[kc * 32 + kk];   // warp-broadcast
            float t1 = r1[kc * 32 + kk];
            acc0 += t0 * wv;
            acc1 += t1 * wv;
        }
        __syncthreads();
    }
    int n0 = base + w * 2, n1 = n0 + 1;
    if (n0 < N_NODESC) out[n0 * 32 + l] = acc0 * C_V;
    if (n1 < N_NODESC) out[n1 * 32 + l] = acc1 * C_V;
}

// ---------------- launch: single stream, 6 kernels ----------------
extern "C" void kernel_launch(void* const* d_in, const int* in_sizes, int n_in,
                              void* d_out, int out_size) {
    (void)in_sizes; (void)n_in; (void)out_size;
    const float* x    = (const float*)d_in[0];
    const float* pos  = (const float*)d_in[1];
    const float* Wq   = (const float*)d_in[2];
    const float* Wk1  = (const float*)d_in[3];
    const float* Wk2  = (const float*)d_in[4];
    const float* Wv1  = (const float*)d_in[5];
    const float* Wv2  = (const float*)d_in[6];
    const float* Wdot = (const float*)d_in[7];
    const int* esrc   = (const int*)d_in[8];
    const int* edst   = (const int*)d_in[9];
    float* out = (float*)d_out;

    k_hist<<<(N_EDGESC + 255) / 256, 256>>>(edst);                 // 1
    k_scan<<<1, 1024>>>();                                         // 2
    k_scatter<<<(N_EDGESC + 255) / 256, 256>>>(esrc, edst);        // 3
    k_R<<<N_NODESC / RT_NODES, 384>>>(x, Wq, Wdot, Wk2);           // 4
    k_passA<<<(N_EDGESC + 255) / 256, 256>>>(x, pos, Wk1, Wv1);    // 5
    k_passBout<<<(N_NODESC + BN - 1) / BN, 448>>>(Wv2, out);       // 6
}

// round 12
// speedup vs baseline: 1.8602x; 1.0478x over previous
#include <cuda_runtime.h>
#include <math.h>

#define N_NODESC 20000
#define N_EDGESC 120000
#define HY_STRIDE 44

// ---- static device scratch (zero-initialized at module load) ----
__device__ int   g_deg[N_NODESC];     // zero invariant restored by k_scatter each run
__device__ int   g_off[N_NODESC + 1];
__device__ int   g_cursor[N_NODESC];
__device__ int2  g_edge[N_EDGESC];               // sorted (src,dst)
__device__ float g_MW[16 * 384];                 // MW[p][t], t=j*24+u (computed in k_hist blk 0)
__device__ float g_R[(size_t)N_NODESC * 384];    // R[n][j*24+u]
__device__ float g_hy[(size_t)N_EDGESC * HY_STRIDE + 16]; // per SORTED slot: hv'[16], y[24], expv

#define C_EMB   8.4335730690754870f
#define C_V     0.05103103630798287f
#define C_LOGIT 0.003189439769248930f

__device__ __forceinline__ float susf(float v) {
    return (v > 0.f) ? __expf(-__fdividef(1.f, v)) : 0.f;
}
__device__ __forceinline__ float siluf(float z) {
    return __fdividef(z, 1.f + __expf(-z));
}

// ---------------- hist (+ block 0 computes MW once) ----------------
__global__ void k_hist(const int* __restrict__ dst, const float* __restrict__ Wq,
                       const float* __restrict__ Wdot, const float* __restrict__ Wk2) {
    int i = blockIdx.x * 384 + threadIdx.x;
    if (i < N_EDGESC) atomicAdd(&g_deg[dst[i]], 1);

    if (blockIdx.x == 0) {
        __shared__ float sM[16][17];
        int t = threadIdx.x;  // 0..383
        if (t < 256) {
            int p = t >> 4, w = t & 15;
            float a = 0.f;
            #pragma unroll
            for (int r = 0; r < 16; r++) a += __ldg(&Wq[p * 16 + r]) * __ldg(&Wdot[r * 16 + w]);
            sM[p][w] = a * 0.25f * C_LOGIT;
        }
        __syncthreads();
        int j = t / 24, u = t - j * 24;
        float wk[16];
        #pragma unroll
        for (int w = 0; w < 16; w++) wk[w] = __ldg(&Wk2[j * 384 + u * 16 + w]);
        #pragma unroll
        for (int p = 0; p < 16; p++) {
            float a = 0.f;
            #pragma unroll
            for (int w = 0; w < 16; w++) a += sM[p][w] * wk[w];
            g_MW[p * 384 + t] = a;
        }
    }
}

__global__ void k_scan() {
    __shared__ int s[1024];
    int tid = threadIdx.x;
    const int CH = (N_NODESC + 1023) / 1024;  // 20
    int base = tid * CH;
    int sum = 0;
    #pragma unroll
    for (int c = 0; c < CH; c++) {
        int idx = base + c;
        if (idx < N_NODESC) sum += g_deg[idx];
    }
    s[tid] = sum;
    __syncthreads();
    for (int d = 1; d < 1024; d <<= 1) {
        int v = (tid >= d) ? s[tid - d] : 0;
        __syncthreads();
        s[tid] += v;
        __syncthreads();
    }
    int run = s[tid] - sum;
    for (int c = 0; c < CH; c++) {
        int idx = base + c;
        if (idx < N_NODESC) {
            g_off[idx] = run;
            g_cursor[idx] = run;
            run += g_deg[idx];
        }
    }
    if (tid == 1023) g_off[N_NODESC] = s[1023];
}

// scatter + re-zero g_deg (restores zero invariant for the next graph replay)
__global__ void k_scatter(const int* __restrict__ src, const int* __restrict__ dst) {
    int i = blockIdx.x * blockDim.x + threadIdx.x;
    if (i < N_EDGESC) {
        int d = dst[i];
        int p = atomicAdd(&g_cursor[d], 1);
        g_edge[p] = make_int2(src[i], d);
        if (i < N_NODESC) g_deg[i] = 0;
    }
}

// ---------------- R GEMM: R[n][t] = sum_p x0[n][p]*MW[p][t] ----------------
// 800 blocks x 384 threads, 25 nodes/block, weights in registers, 4 partial chains.
#define RT_NODES 25
__global__ void k_R(const float* __restrict__ x) {
    __shared__ float sq[RT_NODES * 16];
    int t = threadIdx.x;  // 0..383

    float wr[16];
    #pragma unroll
    for (int p = 0; p < 16; p++) wr[p] = g_MW[p * 384 + t];   // coalesced, L2-hot

    int nb = blockIdx.x * RT_NODES;
    for (int i = t; i < RT_NODES * 16; i += 384) {
        int n = i >> 4, c = i & 15;
        sq[i] = x[(size_t)(nb + n) * 40 + c];
    }
    __syncthreads();

    float* Rp = g_R + (size_t)nb * 384 + t;
    #pragma unroll 5
    for (int n0 = 0; n0 < RT_NODES; n0++) {
        const float4* q4 = (const float4*)(sq + n0 * 16);
        float4 qa = q4[0], qb = q4[1], qc = q4[2], qd = q4[3];
        float s0 = wr[0] * qa.x;  float s1 = wr[1] * qa.y;
        float s2 = wr[2] * qa.z;  float s3 = wr[3] * qa.w;
        s0 += wr[4] * qb.x;  s1 += wr[5] * qb.y;
        s2 += wr[6] * qb.z;  s3 += wr[7] * qb.w;
        s0 += wr[8] * qc.x;  s1 += wr[9] * qc.y;
        s2 += wr[10] * qc.z; s3 += wr[11] * qc.w;
        s0 += wr[12] * qd.x; s1 += wr[13] * qd.y;
        s2 += wr[14] * qd.z; s3 += wr[15] * qd.w;
        Rp[(size_t)n0 * 384] = (s0 + s1) + (s2 + s3);
    }
}

// ---------------- pass A: SORTED edge order (R-row L1 broadcast locality) ----------------
__global__ void k_passA(const float* __restrict__ x, const float* __restrict__ pos,
                        const float* __restrict__ Wk1, const float* __restrict__ Wv1) {
    __shared__ float s_wkv[320];
    {
        int tt = threadIdx.x;
        if (tt < 160) { s_wkv[tt] = __ldg(&Wk1[tt]); s_wkv[160 + tt] = __ldg(&Wv1[tt]); }
    }
    __syncthreads();

    int i = blockIdx.x * blockDim.x + threadIdx.x;
    if (i >= N_EDGESC) return;
    int2 sd = g_edge[i];
    int s = sd.x, d = sd.y;
    float* row = g_hy + (size_t)i * HY_STRIDE;

    float ev0 = pos[s * 3 + 0] - pos[d * 3 + 0];
    float ev1 = pos[s * 3 + 1] - pos[d * 3 + 1];
    float ev2 = pos[s * 3 + 2] - pos[d * 3 + 2];
    float elen = sqrtf(ev0 * ev0 + ev1 * ev1 + ev2 * ev2 + 1e-12f);

    float wcut = susf(10.f * (1.f - elen * 0.25f));
    if (!(wcut > 0.f)) {
        float4 z4 = make_float4(0.f, 0.f, 0.f, 0.f);
        ((float4*)row)[0] = z4; ((float4*)row)[1] = z4;
        ((float4*)row)[2] = z4; ((float4*)row)[3] = z4;
        ((float4*)row)[10] = z4;
        return;
    }

    float tt = elen * 2.75f;
    int b0 = (int)tt;
    float d0 = tt - (float)b0;
    float g0 = (b0 >= 1 && b0 <= 10) ? (C_EMB * susf(d0 + 1.f) * susf(1.f - d0)) : 0.f;
    float g1 = (b0 >= 0 && b0 <= 9)  ? (C_EMB * susf(d0) * susf(2.f - d0)) : 0.f;
    int r0 = b0 - 1; if (r0 < 0) r0 = 0; if (r0 > 9) r0 = 9;
    int r1 = b0;     if (r1 < 0) r1 = 0; if (r1 > 9) r1 = 9;

    float4 xr[10];
    const float4* xp4 = (const float4*)(x + (size_t)s * 40);
    #pragma unroll
    for (int q = 0; q < 10; q++) xr[q] = __ldg(&xp4[q]);
    const float* xf = (const float*)xr;

    float y[24];
    float rinv = __frcp_rn(elen);
    #pragma unroll
    for (int u = 0; u < 16; u++) y[u] = xf[u];
    #pragma unroll
    for (int u = 0; u < 8; u++)
        y[16 + u] = (xf[16 + u * 3] * ev0 + xf[17 + u * 3] * ev1 + xf[18 + u * 3] * ev2) * rinv;

    float lg = 0.f;
    const float4* Rp = (const float4*)(g_R + (size_t)d * 384);
    #pragma unroll
    for (int j = 0; j < 16; j++) {
        float zk = g0 * s_wkv[r0 * 16 + j] + g1 * s_wkv[r1 * 16 + j];
        float hk = siluf(zk);
        float Sj = 0.f;
        #pragma unroll
        for (int q4 = 0; q4 < 6; q4++) {
            float4 r4 = __ldg(&Rp[j * 6 + q4]);
            Sj += r4.x * y[q4 * 4 + 0] + r4.y * y[q4 * 4 + 1]
                + r4.z * y[q4 * 4 + 2] + r4.w * y[q4 * 4 + 3];
        }
        lg += hk * Sj;
    }
    float expv = wcut * __expf(lg);
    float sev = sqrtf(expv);

    #pragma unroll
    for (int j4 = 0; j4 < 4; j4++) {
        float h0 = sev * siluf(g0 * s_wkv[160 + r0 * 16 + j4 * 4 + 0] + g1 * s_wkv[160 + r1 * 16 + j4 * 4 + 0]);
        float h1 = sev * siluf(g0 * s_wkv[160 + r0 * 16 + j4 * 4 + 1] + g1 * s_wkv[160 + r1 * 16 + j4 * 4 + 1]);
        float h2 = sev * siluf(g0 * s_wkv[160 + r0 * 16 + j4 * 4 + 2] + g1 * s_wkv[160 + r1 * 16 + j4 * 4 + 2]);
        float h3 = sev * siluf(g0 * s_wkv[160 + r0 * 16 + j4 * 4 + 3] + g1 * s_wkv[160 + r1 * 16 + j4 * 4 + 3]);
        ((float4*)row)[j4] = make_float4(h0, h1, h2, h3);
    }
    #pragma unroll
    for (int q4 = 0; q4 < 6; q4++)
        ((float4*)(row + 16))[q4] = make_float4(y[q4 * 4 + 0], y[q4 * 4 + 1],
                                                y[q4 * 4 + 2], y[q4 * 4 + 3]);
    ((float4*)row)[10] = make_float4(expv, 0.f, 0.f, 0.f);
}

// ---------------- fused pass B + output GEMM ----------------
#define BN 28
__global__ void __launch_bounds__(448)
k_passBout(const float* __restrict__ Wv2, float* __restrict__ out) {
    __shared__ float sT[BN][384];     // 43,008 B
    __shared__ float sWt[32][34];     // [k_local][col], pad 2

    int t = threadIdx.x;
    int l = t & 31, w = t >> 5;       // warp 0..13
    int base = blockIdx.x * BN;
    int par = l >> 4;
    int jj = l & 15;

    // ---- phase 1: passB ----
    #pragma unroll
    for (int q = 0; q < 2; q++) {
        int n = base + w * 2 + q;
        float acc[12];
        #pragma unroll
        for (int k = 0; k < 12; k++) acc[k] = 0.f;
        float z = 0.f;

        if (n < N_NODESC) {
            int beg = g_off[n], end = g_off[n + 1];
            if (beg < end) {
                const float* row = g_hy + (size_t)beg * HY_STRIDE;
                float A = row[l];
                float B = (l < 16) ? row[32 + l] : 0.f;
                for (int i = beg; i < end; i++) {
                    float A2 = 0.f, B2 = 0.f;
                    if (i + 1 < end) {
                        const float* row2 = g_hy + (size_t)(i + 1) * HY_STRIDE;
                        A2 = row2[l];
                        B2 = (l < 16) ? row2[32 + l] : 0.f;
                    }
                    z += __shfl_sync(0xffffffffu, B, 8);
                    float hval = __shfl_sync(0xffffffffu, A, jj);
                    #pragma unroll
                    for (int k = 0; k < 8; k++) {
                        float yv = __shfl_sync(0xffffffffu, A, 16 + par + 2 * k);
                        acc[k] += hval * yv;
                    }
                    #pragma unroll
                    for (int k = 8; k < 12; k++) {
                        float yv = __shfl_sync(0xffffffffu, B, par + 2 * k - 16);
                        acc[k] += hval * yv;
                    }
                    A = A2; B = B2;
                }
            }
        }
        if (z == 0.f) z = 1.f;
        float sc = rsqrtf(z);
        #pragma unroll
        for (int k = 0; k < 12; k++) sT[w * 2 + q][l + 32 * k] = acc[k] * sc;
    }
    __syncthreads();

    // ---- phase 2: GEMM out = C_V * sT @ W' ----
    float acc0 = 0.f, acc1 = 0.f;
    const float* r0 = sT[w * 2];
    const float* r1 = sT[w * 2 + 1];
    for (int kc = 0; kc < 12; kc++) {
        for (int i = t; i < 1024; i += 448) {
            int kk = i >> 5, col = i & 31;
            int k = kc * 32 + kk;
            sWt[kk][col] = __ldg(&Wv2[(k & 15) * 768 + (k >> 4) * 32 + col]);
        }
        __syncthreads();
        #pragma unroll 8
        for (int kk = 0; kk < 32; kk++) {
            float wv = sWt[kk][l];
            float t0 = r0[kc * 32 + kk];   // warp-broadcast
            float t1 = r1[kc * 32 + kk];
            acc0 += t0 * wv;
            acc1 += t1 * wv;
        }
        __syncthreads();
    }
    int n0 = base + w * 2, n1 = n0 + 1;
    if (n0 < N_NODESC) out[n0 * 32 + l] = acc0 * C_V;
    if (n1 < N_NODESC) out[n1 * 32 + l] = acc1 * C_V;
}

// ---------------- launch: single stream, 6 kernels ----------------
extern "C" void kernel_launch(void* const* d_in, const int* in_sizes, int n_in,
                              void* d_out, int out_size) {
    (void)in_sizes; (void)n_in; (void)out_size;
    const float* x    = (const float*)d_in[0];
    const float* pos  = (const float*)d_in[1];
    const float* Wq   = (const float*)d_in[2];
    const float* Wk1  = (const float*)d_in[3];
    const float* Wk2  = (const float*)d_in[4];
    const float* Wv1  = (const float*)d_in[5];
    const float* Wv2  = (const float*)d_in[6];
    const float* Wdot = (const float*)d_in[7];
    const int* esrc   = (const int*)d_in[8];
    const int* edst   = (const int*)d_in[9];
    float* out = (float*)d_out;

    k_hist<<<(N_EDGESC + 383) / 384, 384>>>(edst, Wq, Wdot, Wk2); // 1
    k_scan<<<1, 1024>>>();                                         // 2
    k_scatter<<<(N_EDGESC + 255) / 256, 256>>>(esrc, edst);        // 3
    k_R<<<N_NODESC / RT_NODES, 384>>>(x);                          // 4 (profiled)
    k_passA<<<(N_EDGESC + 255) / 256, 256>>>(x, pos, Wk1, Wv1);    // 5
    k_passBout<<<(N_NODESC + BN - 1) / BN, 448>>>(Wv2, out);       // 6
}